// round 12
// baseline (speedup 1.0000x reference)
#include <cuda_runtime.h>
#include <cuda_bf16.h>
#include <cstdint>

#define BQ    1024
#define QMAX  32768
#define DIM   256
#define PERP  15
#define CANDMAX 256
#define DELTA 8.0f
#define QSCALE 20.0f            // int8 quant scale
#define INV_S2 (1.0f/200.0f)    // 2 / (QSCALE*QSCALE)
#define CAP   2048
#define TAU_Z 2.5f

// ---------------- scratch ----------------------------------------------------
__device__ __align__(16) int8_t g_q8[(size_t)QMAX * DIM];
__device__ float g_y2[QMAX];
__device__ unsigned long long g_cand[(size_t)BQ * CAP];
__device__ int   g_cnt[BQ];

// ---------------- prep -------------------------------------------------------
__global__ void __launch_bounds__(256) prep_kernel(const float* __restrict__ data,
                                                   const float* __restrict__ queue) {
    const int t    = threadIdx.x;
    const int row  = blockIdx.x * 4 + (t >> 6);
    const int l    = t & 63;
    const float* src = (row < BQ) ? (data + (size_t)row * DIM)
                                  : (queue + (size_t)(row - BQ) * DIM);
    float4 v = *(const float4*)(src + l * 4);

    int q0 = __float2int_rn(fminf(fmaxf(v.x * QSCALE, -127.f), 127.f));
    int q1 = __float2int_rn(fminf(fmaxf(v.y * QSCALE, -127.f), 127.f));
    int q2 = __float2int_rn(fminf(fmaxf(v.z * QSCALE, -127.f), 127.f));
    int q3 = __float2int_rn(fminf(fmaxf(v.w * QSCALE, -127.f), 127.f));
    uint32_t packed = (uint32_t)(q0 & 0xff) | ((uint32_t)(q1 & 0xff) << 8) |
                      ((uint32_t)(q2 & 0xff) << 16) | ((uint32_t)(q3 & 0xff) << 24);
    *(uint32_t*)(&g_q8[(size_t)row * DIM + l * 4]) = packed;

    float s = v.x*v.x + v.y*v.y + v.z*v.z + v.w*v.w;
    #pragma unroll
    for (int o = 16; o; o >>= 1) s += __shfl_xor_sync(0xffffffffu, s, o);
    __shared__ float ws[8];
    if ((t & 31) == 0) ws[t >> 5] = s;
    __syncthreads();
    if (l == 0) {
        g_y2[row] = ws[(t >> 6) * 2] + ws[(t >> 6) * 2 + 1];
        if (row < BQ) g_cnt[row] = 0;
    }
}

// ---------------- hybrid GEMM: MMA pipe (cols 0-79) + dp4a ALU pipe (80-127) --
#define BK      64
#define ROW_STR 80
#define STG     (128 * ROW_STR)
#define OFF_A   0
#define OFF_B   (4 * STG)
#define OFF_Y2  (8 * STG)
#define OFF_TAU (OFF_Y2 + 128 * 4)
#define GSMEM   (OFF_TAU + 128 * 4)

__device__ __forceinline__ uint32_t smem_u32(const void* p) {
    uint32_t a;
    asm("{ .reg .u64 t; cvta.to.shared.u64 t, %1; cvt.u32.u64 %0, t; }" : "=r"(a) : "l"(p));
    return a;
}
#define CP_ASYNC16(dst, src) \
    asm volatile("cp.async.cg.shared.global [%0], [%1], 16;" :: "r"(dst), "l"(src))
#define CP_COMMIT() asm volatile("cp.async.commit_group;" ::: "memory")
#define CP_WAIT(n)  asm volatile("cp.async.wait_group %0;" :: "n"(n) : "memory")
#define LDS128U(r0, r1, r2, r3, addr) \
    asm volatile("ld.shared.v4.u32 {%0,%1,%2,%3}, [%4];" \
                 : "=r"(r0), "=r"(r1), "=r"(r2), "=r"(r3) : "r"(addr))

__device__ __forceinline__ int dp4a_s32(uint32_t a, uint32_t b, int c) {
    int d;
    asm("dp4a.s32.s32 %0, %1, %2, %3;" : "=r"(d) : "r"(a), "r"(b), "r"(c));
    return d;
}
__device__ __forceinline__ void ldsm_x4(uint32_t& r0, uint32_t& r1, uint32_t& r2,
                                        uint32_t& r3, uint32_t addr) {
    asm volatile("ldmatrix.sync.aligned.m8n8.x4.shared.b16 {%0,%1,%2,%3}, [%4];"
                 : "=r"(r0), "=r"(r1), "=r"(r2), "=r"(r3) : "r"(addr));
}
__device__ __forceinline__ void ldsm_x2(uint32_t& r0, uint32_t& r1, uint32_t addr) {
    asm volatile("ldmatrix.sync.aligned.m8n8.x2.shared.b16 {%0,%1}, [%2];"
                 : "=r"(r0), "=r"(r1) : "r"(addr));
}
__device__ __forceinline__ void mma_s8(int c[4], uint32_t a0, uint32_t a1,
                                       uint32_t a2, uint32_t a3,
                                       uint32_t b0, uint32_t b1) {
    asm volatile(
        "mma.sync.aligned.m16n8k32.row.col.s32.s8.s8.s32 "
        "{%0,%1,%2,%3}, {%4,%5,%6,%7}, {%8,%9}, {%0,%1,%2,%3};\n"
        : "+r"(c[0]), "+r"(c[1]), "+r"(c[2]), "+r"(c[3])
        : "r"(a0), "r"(a1), "r"(a2), "r"(a3), "r"(b0), "r"(b1));
}
__device__ __forceinline__ unsigned long long make_key(float v, int j) {
    unsigned u = __float_as_uint(v);
    u = (u & 0x80000000u) ? ~u : (u | 0x80000000u);
    return ((unsigned long long)u << 32) | (unsigned)j;
}
__device__ __forceinline__ float key_val(unsigned long long k) {
    unsigned s = (unsigned)(k >> 32);
    unsigned u = (s & 0x80000000u) ? (s ^ 0x80000000u) : ~s;
    return __uint_as_float(u);
}
__device__ __forceinline__ void emit_cand(float v, int ri, int cj, float tau) {
    if (v < tau && cj != ri) {
        int p = atomicAdd(&g_cnt[ri], 1);
        if (p < CAP) g_cand[(size_t)ri * CAP + p] = make_key(v, cj);
    }
}

__global__ void __launch_bounds__(256, 2) gemm_kernel() {
    extern __shared__ __align__(16) char smem[];
    const uint32_t sb = smem_u32(smem);
    float* sy2  = (float*)(smem + OFF_Y2);
    float* stau = (float*)(smem + OFF_TAU);

    const int t    = threadIdx.x;
    const int lane = t & 31, wid = t >> 5;
    const int bm   = blockIdx.y * 128;
    const int bn   = blockIdx.x * 128;

    // prologue: stage ALL of A and B (K=256 in 4 chunk-stages each)
    #pragma unroll
    for (int kc = 0; kc < 4; kc++) {
        const uint32_t abuf = sb + OFF_A + kc * STG;
        const uint32_t bbuf = sb + OFF_B + kc * STG;
        #pragma unroll
        for (int i = t; i < 512; i += 256) {
            const int r = i >> 2, c = i & 3;
            CP_ASYNC16(abuf + (uint32_t)(r * ROW_STR + c * 16),
                       (const char*)&g_q8[(size_t)(bm + r) * DIM + kc * BK + c * 16]);
        }
        #pragma unroll
        for (int i = t; i < 512; i += 256) {
            const int r = i >> 2, c = i & 3;
            CP_ASYNC16(bbuf + (uint32_t)(r * ROW_STR + c * 16),
                       (const char*)&g_q8[(size_t)(bn + r) * DIM + kc * BK + c * 16]);
        }
    }
    CP_COMMIT();

    if (t < 32) *(float4*)&sy2[t * 4] = *(const float4*)&g_y2[bn + t * 4];
    if (t < 128) {
        const float x2 = g_y2[bm + t];
        stau[t] = 256.0f - TAU_Z * sqrtf(fmaf(4.0f, x2, 512.0f));
    }

    CP_WAIT(0);
    __syncthreads();            // everything staged; roles now run independently

    if (wid < 4) {
        // ======== MMA warps: cols 0..79, warp tile 64x40 (2m x 2n) ========
        const int wm = (wid >> 1) * 64;
        const int wn = (wid & 1) * 40;
        const int gid = lane >> 2, tig = lane & 3;

        int acc[4][5][4];
        #pragma unroll
        for (int mi = 0; mi < 4; mi++)
            #pragma unroll
            for (int ni = 0; ni < 5; ni++)
                #pragma unroll
                for (int e = 0; e < 4; e++) acc[mi][ni][e] = 0;

        #pragma unroll
        for (int kt = 0; kt < 4; kt++) {
            const uint32_t abuf = sb + OFF_A + kt * STG;
            const uint32_t bbuf = sb + OFF_B + kt * STG;
            #pragma unroll
            for (int kk = 0; kk < BK; kk += 32) {
                uint32_t a[4][4], b[5][2];
                const int acol = kk + ((lane >> 4) << 4);
                #pragma unroll
                for (int mi = 0; mi < 4; mi++) {
                    const int ar = wm + mi * 16 + (lane & 15);
                    ldsm_x4(a[mi][0], a[mi][1], a[mi][2], a[mi][3],
                            abuf + (uint32_t)(ar * ROW_STR + acol));
                }
                const int bcol = kk + (((lane >> 3) & 1) << 4);
                #pragma unroll
                for (int nj = 0; nj < 4; nj += 2) {
                    const int br = wn + nj * 8 + (lane & 7) + ((lane >> 4) << 3);
                    ldsm_x4(b[nj][0], b[nj][1], b[nj + 1][0], b[nj + 1][1],
                            bbuf + (uint32_t)(br * ROW_STR + bcol));
                }
                {
                    const int br = wn + 32 + (lane & 7) + ((lane >> 4) << 3);
                    ldsm_x2(b[4][0], b[4][1],
                            bbuf + (uint32_t)(br * ROW_STR + bcol));
                }
                #pragma unroll
                for (int mi = 0; mi < 4; mi++)
                    #pragma unroll
                    for (int ni = 0; ni < 5; ni++)
                        mma_s8(acc[mi][ni], a[mi][0], a[mi][1], a[mi][2], a[mi][3],
                               b[ni][0], b[ni][1]);
            }
        }

        #pragma unroll
        for (int mi = 0; mi < 4; mi++) {
            const int lr = wm + mi * 16 + gid;
            const float tau0 = stau[lr], tau1 = stau[lr + 8];
            #pragma unroll
            for (int ni = 0; ni < 5; ni++) {
                const int lc = wn + ni * 8 + tig * 2;
                const float y0 = sy2[lc], y1 = sy2[lc + 1];
                emit_cand(fmaf(-INV_S2, (float)acc[mi][ni][0], y0), bm + lr,     bn + lc,     tau0);
                emit_cand(fmaf(-INV_S2, (float)acc[mi][ni][1], y1), bm + lr,     bn + lc + 1, tau0);
                emit_cand(fmaf(-INV_S2, (float)acc[mi][ni][2], y0), bm + lr + 8, bn + lc,     tau1);
                emit_cand(fmaf(-INV_S2, (float)acc[mi][ni][3], y1), bm + lr + 8, bn + lc + 1, tau1);
            }
        }
    } else {
        // ======== dp4a warps: cols 80..127 (48), per thread 16 rows x 3 cols ==
        const int dt  = t - 128;                 // 0..127
        const int cg  = dt & 15;                 // col group (3 cols each)
        const int rgb = (dt >> 4) * 16;          // row base
        const int c0  = 80 + cg * 3;             // first of 3 cols

        int accd[16][3];
        #pragma unroll
        for (int rr = 0; rr < 16; rr++)
            #pragma unroll
            for (int j = 0; j < 3; j++) accd[rr][j] = 0;

        for (int kk = 0; kk < 16; kk++) {        // 16-byte k-chunks, rotated by 2*cg
            const int kc = (kk + 2 * cg) & 15;
            const uint32_t base = sb + (uint32_t)((kc >> 2) * STG + (kc & 3) * 16);

            uint32_t bw[3][4];
            #pragma unroll
            for (int j = 0; j < 3; j++)
                LDS128U(bw[j][0], bw[j][1], bw[j][2], bw[j][3],
                        base + OFF_B + (uint32_t)((c0 + j) * ROW_STR));

            #pragma unroll
            for (int r4 = 0; r4 < 4; r4++) {
                uint32_t aw[4][4];
                #pragma unroll
                for (int i = 0; i < 4; i++)
                    LDS128U(aw[i][0], aw[i][1], aw[i][2], aw[i][3],
                            base + OFF_A + (uint32_t)((rgb + r4 * 4 + i) * ROW_STR));
                #pragma unroll
                for (int i = 0; i < 4; i++)
                    #pragma unroll
                    for (int j = 0; j < 3; j++) {
                        int s = accd[r4 * 4 + i][j];
                        s = dp4a_s32(aw[i][0], bw[j][0], s);
                        s = dp4a_s32(aw[i][1], bw[j][1], s);
                        s = dp4a_s32(aw[i][2], bw[j][2], s);
                        s = dp4a_s32(aw[i][3], bw[j][3], s);
                        accd[r4 * 4 + i][j] = s;
                    }
            }
        }

        #pragma unroll
        for (int rr = 0; rr < 16; rr++) {
            const int lr = rgb + rr;
            const float tau = stau[lr];
            #pragma unroll
            for (int j = 0; j < 3; j++) {
                const int lc = c0 + j;
                emit_cand(fmaf(-INV_S2, (float)accd[rr][j], sy2[lc]),
                          bm + lr, bn + lc, tau);
            }
        }
    }
}

// ---------------- select: candidate list -> approx top-15 -> exact -----------
__global__ void __launch_bounds__(256) select_kernel(const float* __restrict__ data,
                                                     const float* __restrict__ queue,
                                                     const int* __restrict__ jdx,
                                                     float* __restrict__ out) {
    __shared__ unsigned long long skeys[256 * PERP];
    __shared__ unsigned long long swarp[8];
    __shared__ unsigned long long s_bcast;
    __shared__ unsigned long long sx[PERP];
    __shared__ __align__(16) float sdata[DIM];
    __shared__ int   cand[CANDMAX];
    __shared__ unsigned long long ckeys[CANDMAX];
    __shared__ int   s_cnt, s_nbr;

    const int row = blockIdx.x;
    const int t   = threadIdx.x;
    const int cnt0 = min(g_cnt[row], CAP);
    const unsigned long long* crow = g_cand + (size_t)row * CAP;

    if (t == 0) s_cnt = PERP;
    sdata[t] = data[(size_t)row * DIM + t];

    unsigned long long keys[PERP];
    #pragma unroll
    for (int i = 0; i < PERP; i++) keys[i] = ~0ULL;
    for (int j = t; j < cnt0; j += 256) {
        unsigned long long key = crow[j];
        if (key < keys[PERP - 1]) {
            #pragma unroll
            for (int i = PERP - 1; i >= 1; i--) {
                unsigned long long up = keys[i - 1];
                keys[i] = (key < up) ? up : ((key < keys[i]) ? key : keys[i]);
            }
            keys[0] = (key < keys[0]) ? key : keys[0];
        }
    }
    #pragma unroll
    for (int i = 0; i < PERP; i++) skeys[t * PERP + i] = keys[i];
    __syncthreads();

    for (int it = 0; it < PERP; it++) {
        unsigned long long m = ~0ULL;
        #pragma unroll
        for (int i = 0; i < PERP; i++) {
            unsigned long long v = skeys[t + i * 256];
            m = (v < m) ? v : m;
        }
        #pragma unroll
        for (int o = 16; o; o >>= 1) {
            unsigned long long other = __shfl_xor_sync(0xffffffffu, m, o);
            m = (other < m) ? other : m;
        }
        if ((t & 31) == 0) swarp[t >> 5] = m;
        __syncthreads();
        if (t == 0) {
            unsigned long long mm = swarp[0];
            #pragma unroll
            for (int i = 1; i < 8; i++) mm = (swarp[i] < mm) ? swarp[i] : mm;
            s_bcast = mm;
            sx[it]  = mm;
        }
        __syncthreads();
        unsigned long long cur = s_bcast;
        #pragma unroll
        for (int i = 0; i < PERP; i++) {
            int idx = t + i * 256;
            if (skeys[idx] == cur) skeys[idx] = ~0ULL;
        }
        __syncthreads();
    }

    const unsigned long long tkey = make_key(key_val(sx[PERP - 1]) + DELTA, 0);
    if (t < PERP) cand[t] = (int)(sx[t] & 0xffffffffu);
    #pragma unroll
    for (int i = 0; i < PERP; i++) {
        unsigned long long v = skeys[t + i * 256];
        if (v < tkey) {
            int p = atomicAdd(&s_cnt, 1);
            if (p < CANDMAX) cand[p] = (int)(v & 0xffffffffu);
        }
    }
    __syncthreads();
    const int cnt = (s_cnt < CANDMAX) ? s_cnt : CANDMAX;

    {
        const int lane = t & 31, wid = t >> 5;
        for (int c = wid; c < cnt; c += 8) {
            const int j = cand[c];
            const float* qj = (j < BQ) ? (data + (size_t)j * DIM)
                                       : (queue + (size_t)(j - BQ) * DIM);
            float4 x0 = *(const float4*)&sdata[lane * 8];
            float4 x1 = *(const float4*)&sdata[lane * 8 + 4];
            float4 y0 = *(const float4*)&qj[lane * 8];
            float4 y1 = *(const float4*)&qj[lane * 8 + 4];
            float d = x0.x*y0.x + x0.y*y0.y + x0.z*y0.z + x0.w*y0.w
                    + x1.x*y1.x + x1.y*y1.y + x1.z*y1.z + x1.w*y1.w;
            #pragma unroll
            for (int o = 16; o; o >>= 1) d += __shfl_xor_sync(0xffffffffu, d, o);
            if (lane == 0) ckeys[c] = make_key(fmaf(-2.0f, d, g_y2[j]), j);
        }
    }
    __syncthreads();

    const int r = jdx[row];
    if (t < cnt) {
        unsigned long long mykey = ckeys[t];
        int rank = 0;
        for (int d = 0; d < cnt; d++) rank += (ckeys[d] < mykey);
        if (rank == r) s_nbr = cand[t];
    }
    __syncthreads();
    const int nbr = s_nbr;
    const float* srow = (nbr < BQ) ? (data + (size_t)nbr * DIM)
                                   : (queue + (size_t)(nbr - BQ) * DIM);
    out[(size_t)row * DIM + t] = srow[t];
}

// ---------------- launch -----------------------------------------------------
extern "C" void kernel_launch(void* const* d_in, const int* in_sizes, int n_in,
                              void* d_out, int out_size) {
    (void)in_sizes; (void)n_in; (void)out_size;
    const float* data  = (const float*)d_in[0];
    const float* queue = (const float*)d_in[1];
    const int*   jdx   = (const int*)d_in[2];
    float*       out   = (float*)d_out;

    cudaFuncSetAttribute(gemm_kernel, cudaFuncAttributeMaxDynamicSharedMemorySize, GSMEM);

    prep_kernel<<<QMAX / 4, 256>>>(data, queue);
    gemm_kernel<<<dim3(QMAX / 128, BQ / 128), 256, GSMEM>>>();
    select_kernel<<<BQ, 256>>>(data, queue, jdx, out);
}

// round 13
// speedup vs baseline: 1.4464x; 1.4464x over previous
#include <cuda_runtime.h>
#include <cuda_bf16.h>
#include <cstdint>

#define BQ    1024
#define QMAX  32768
#define DIM   256
#define PERP  15
#define CANDMAX 256
#define DELTA 8.0f
#define QSCALE 20.0f            // int8 quant scale
#define INV_S2 (1.0f/200.0f)    // 2 / (QSCALE*QSCALE)
#define CAP   2048
#define TAU_Z 2.5f

// ---------------- scratch ----------------------------------------------------
__device__ __align__(16) int8_t g_q8[(size_t)QMAX * DIM];
__device__ float g_y2[QMAX];
__device__ unsigned long long g_cand[(size_t)BQ * CAP];
__device__ int   g_cnt[BQ];

// ---------------- prep -------------------------------------------------------
__global__ void __launch_bounds__(256) prep_kernel(const float* __restrict__ data,
                                                   const float* __restrict__ queue) {
    const int t    = threadIdx.x;
    const int row  = blockIdx.x * 4 + (t >> 6);
    const int l    = t & 63;
    const float* src = (row < BQ) ? (data + (size_t)row * DIM)
                                  : (queue + (size_t)(row - BQ) * DIM);
    float4 v = *(const float4*)(src + l * 4);

    int q0 = __float2int_rn(fminf(fmaxf(v.x * QSCALE, -127.f), 127.f));
    int q1 = __float2int_rn(fminf(fmaxf(v.y * QSCALE, -127.f), 127.f));
    int q2 = __float2int_rn(fminf(fmaxf(v.z * QSCALE, -127.f), 127.f));
    int q3 = __float2int_rn(fminf(fmaxf(v.w * QSCALE, -127.f), 127.f));
    uint32_t packed = (uint32_t)(q0 & 0xff) | ((uint32_t)(q1 & 0xff) << 8) |
                      ((uint32_t)(q2 & 0xff) << 16) | ((uint32_t)(q3 & 0xff) << 24);
    *(uint32_t*)(&g_q8[(size_t)row * DIM + l * 4]) = packed;

    float s = v.x*v.x + v.y*v.y + v.z*v.z + v.w*v.w;
    #pragma unroll
    for (int o = 16; o; o >>= 1) s += __shfl_xor_sync(0xffffffffu, s, o);
    __shared__ float ws[8];
    if ((t & 31) == 0) ws[t >> 5] = s;
    __syncthreads();
    if (l == 0) {
        g_y2[row] = ws[(t >> 6) * 2] + ws[(t >> 6) * 2 + 1];
        if (row < BQ) g_cnt[row] = 0;
    }
}

// ---------------- hybrid GEMM: MMA pipe (cols 0-79) + dp4a ALU pipe (80-127) --
#define BK      64
#define ROW_STR 80
#define STG     (128 * ROW_STR)
#define OFF_A   0
#define OFF_B   (4 * STG)
#define OFF_Y2  (8 * STG)
#define OFF_TAU (OFF_Y2 + 128 * 4)
#define GSMEM   (OFF_TAU + 128 * 4)

__device__ __forceinline__ uint32_t smem_u32(const void* p) {
    uint32_t a;
    asm("{ .reg .u64 t; cvta.to.shared.u64 t, %1; cvt.u32.u64 %0, t; }" : "=r"(a) : "l"(p));
    return a;
}
#define CP_ASYNC16(dst, src) \
    asm volatile("cp.async.cg.shared.global [%0], [%1], 16;" :: "r"(dst), "l"(src))
#define CP_COMMIT() asm volatile("cp.async.commit_group;" ::: "memory")
#define CP_WAIT(n)  asm volatile("cp.async.wait_group %0;" :: "n"(n) : "memory")
#define LDS128U(r0, r1, r2, r3, addr) \
    asm volatile("ld.shared.v4.u32 {%0,%1,%2,%3}, [%4];" \
                 : "=r"(r0), "=r"(r1), "=r"(r2), "=r"(r3) : "r"(addr))

__device__ __forceinline__ int dp4a_s32(uint32_t a, uint32_t b, int c) {
    int d;
    asm("dp4a.s32.s32 %0, %1, %2, %3;" : "=r"(d) : "r"(a), "r"(b), "r"(c));
    return d;
}
__device__ __forceinline__ void ldsm_x4(uint32_t& r0, uint32_t& r1, uint32_t& r2,
                                        uint32_t& r3, uint32_t addr) {
    asm volatile("ldmatrix.sync.aligned.m8n8.x4.shared.b16 {%0,%1,%2,%3}, [%4];"
                 : "=r"(r0), "=r"(r1), "=r"(r2), "=r"(r3) : "r"(addr));
}
__device__ __forceinline__ void ldsm_x2(uint32_t& r0, uint32_t& r1, uint32_t addr) {
    asm volatile("ldmatrix.sync.aligned.m8n8.x2.shared.b16 {%0,%1}, [%2];"
                 : "=r"(r0), "=r"(r1) : "r"(addr));
}
__device__ __forceinline__ void mma_s8(int c[4], uint32_t a0, uint32_t a1,
                                       uint32_t a2, uint32_t a3,
                                       uint32_t b0, uint32_t b1) {
    asm volatile(
        "mma.sync.aligned.m16n8k32.row.col.s32.s8.s8.s32 "
        "{%0,%1,%2,%3}, {%4,%5,%6,%7}, {%8,%9}, {%0,%1,%2,%3};\n"
        : "+r"(c[0]), "+r"(c[1]), "+r"(c[2]), "+r"(c[3])
        : "r"(a0), "r"(a1), "r"(a2), "r"(a3), "r"(b0), "r"(b1));
}
__device__ __forceinline__ unsigned long long make_key(float v, int j) {
    unsigned u = __float_as_uint(v);
    u = (u & 0x80000000u) ? ~u : (u | 0x80000000u);
    return ((unsigned long long)u << 32) | (unsigned)j;
}
__device__ __forceinline__ float key_val(unsigned long long k) {
    unsigned s = (unsigned)(k >> 32);
    unsigned u = (s & 0x80000000u) ? (s ^ 0x80000000u) : ~s;
    return __uint_as_float(u);
}
__device__ __forceinline__ void emit_cand(float v, int ri, int cj, float tau) {
    if (v < tau && cj != ri) {
        int p = atomicAdd(&g_cnt[ri], 1);
        if (p < CAP) g_cand[(size_t)ri * CAP + p] = make_key(v, cj);
    }
}

__global__ void __launch_bounds__(256, 2) gemm_kernel() {
    extern __shared__ __align__(16) char smem[];
    const uint32_t sb = smem_u32(smem);
    float* sy2  = (float*)(smem + OFF_Y2);
    float* stau = (float*)(smem + OFF_TAU);

    const int t    = threadIdx.x;
    const int lane = t & 31, wid = t >> 5;
    const int bm   = blockIdx.y * 128;
    const int bn   = blockIdx.x * 128;

    // prologue: stage ALL of A and B (K=256 in 4 chunk-stages each)
    #pragma unroll
    for (int kc = 0; kc < 4; kc++) {
        const uint32_t abuf = sb + OFF_A + kc * STG;
        const uint32_t bbuf = sb + OFF_B + kc * STG;
        #pragma unroll
        for (int i = t; i < 512; i += 256) {
            const int r = i >> 2, c = i & 3;
            CP_ASYNC16(abuf + (uint32_t)(r * ROW_STR + c * 16),
                       (const char*)&g_q8[(size_t)(bm + r) * DIM + kc * BK + c * 16]);
        }
        #pragma unroll
        for (int i = t; i < 512; i += 256) {
            const int r = i >> 2, c = i & 3;
            CP_ASYNC16(bbuf + (uint32_t)(r * ROW_STR + c * 16),
                       (const char*)&g_q8[(size_t)(bn + r) * DIM + kc * BK + c * 16]);
        }
    }
    CP_COMMIT();

    if (t < 32) *(float4*)&sy2[t * 4] = *(const float4*)&g_y2[bn + t * 4];
    if (t < 128) {
        const float x2 = g_y2[bm + t];
        stau[t] = 256.0f - TAU_Z * sqrtf(fmaf(4.0f, x2, 512.0f));
    }

    CP_WAIT(0);
    __syncthreads();            // everything staged; roles now run independently

    if (wid < 4) {
        // ======== MMA warps: cols 0..79, warp tile 64x40 (2m x 2n) ========
        const int wm = (wid >> 1) * 64;
        const int wn = (wid & 1) * 40;
        const int gid = lane >> 2, tig = lane & 3;

        int acc[4][5][4];
        #pragma unroll
        for (int mi = 0; mi < 4; mi++)
            #pragma unroll
            for (int ni = 0; ni < 5; ni++)
                #pragma unroll
                for (int e = 0; e < 4; e++) acc[mi][ni][e] = 0;

        #pragma unroll
        for (int kt = 0; kt < 4; kt++) {
            const uint32_t abuf = sb + OFF_A + kt * STG;
            const uint32_t bbuf = sb + OFF_B + kt * STG;
            #pragma unroll
            for (int kk = 0; kk < BK; kk += 32) {
                uint32_t a[4][4], b[5][2];
                const int acol = kk + ((lane >> 4) << 4);
                #pragma unroll
                for (int mi = 0; mi < 4; mi++) {
                    const int ar = wm + mi * 16 + (lane & 15);
                    ldsm_x4(a[mi][0], a[mi][1], a[mi][2], a[mi][3],
                            abuf + (uint32_t)(ar * ROW_STR + acol));
                }
                const int bcol = kk + (((lane >> 3) & 1) << 4);
                #pragma unroll
                for (int nj = 0; nj < 4; nj += 2) {
                    const int br = wn + nj * 8 + (lane & 7) + ((lane >> 4) << 3);
                    ldsm_x4(b[nj][0], b[nj][1], b[nj + 1][0], b[nj + 1][1],
                            bbuf + (uint32_t)(br * ROW_STR + bcol));
                }
                {
                    const int br = wn + 32 + (lane & 7) + ((lane >> 4) << 3);
                    ldsm_x2(b[4][0], b[4][1],
                            bbuf + (uint32_t)(br * ROW_STR + bcol));
                }
                #pragma unroll
                for (int mi = 0; mi < 4; mi++)
                    #pragma unroll
                    for (int ni = 0; ni < 5; ni++)
                        mma_s8(acc[mi][ni], a[mi][0], a[mi][1], a[mi][2], a[mi][3],
                               b[ni][0], b[ni][1]);
            }
        }

        #pragma unroll
        for (int mi = 0; mi < 4; mi++) {
            const int lr = wm + mi * 16 + gid;
            const float tau0 = stau[lr], tau1 = stau[lr + 8];
            #pragma unroll
            for (int ni = 0; ni < 5; ni++) {
                const int lc = wn + ni * 8 + tig * 2;
                const float y0 = sy2[lc], y1 = sy2[lc + 1];
                emit_cand(fmaf(-INV_S2, (float)acc[mi][ni][0], y0), bm + lr,     bn + lc,     tau0);
                emit_cand(fmaf(-INV_S2, (float)acc[mi][ni][1], y1), bm + lr,     bn + lc + 1, tau0);
                emit_cand(fmaf(-INV_S2, (float)acc[mi][ni][2], y0), bm + lr + 8, bn + lc,     tau1);
                emit_cand(fmaf(-INV_S2, (float)acc[mi][ni][3], y1), bm + lr + 8, bn + lc + 1, tau1);
            }
        }
    } else {
        // ======== dp4a warps: cols 80..127 (48), thread tile 8 rows x 6 cols ==
        // No k-rotation (round-12 bug): A loads are 4-address/8-lane-broadcast
        // (LDS.128 floor), B loads 8-address/2 bank-sets (2x, acceptable).
        const int dt  = t - 128;                 // 0..127
        const int rg  = dt >> 3;                 // 0..15 -> rows rg*8..rg*8+7
        const int cgp = dt & 7;                  // 0..7  -> cols 80+cgp*6..+5
        const int r0  = rg * 8;
        const int c0  = 80 + cgp * 6;

        int accd[8][6];
        #pragma unroll
        for (int i = 0; i < 8; i++)
            #pragma unroll
            for (int j = 0; j < 6; j++) accd[i][j] = 0;

        for (int kc = 0; kc < 16; kc++) {        // sequential 16B k-chunks
            const uint32_t cb = sb + (uint32_t)((kc >> 2) * STG + (kc & 3) * 16);

            uint32_t bw[6][4];
            #pragma unroll
            for (int j = 0; j < 6; j++)
                LDS128U(bw[j][0], bw[j][1], bw[j][2], bw[j][3],
                        cb + OFF_B + (uint32_t)((c0 + j) * ROW_STR));

            #pragma unroll
            for (int ih = 0; ih < 2; ih++) {     // A in two groups of 4 rows
                uint32_t aw[4][4];
                #pragma unroll
                for (int i = 0; i < 4; i++)
                    LDS128U(aw[i][0], aw[i][1], aw[i][2], aw[i][3],
                            cb + OFF_A + (uint32_t)((r0 + ih * 4 + i) * ROW_STR));
                #pragma unroll
                for (int i = 0; i < 4; i++)
                    #pragma unroll
                    for (int j = 0; j < 6; j++) {
                        int s = accd[ih * 4 + i][j];
                        s = dp4a_s32(aw[i][0], bw[j][0], s);
                        s = dp4a_s32(aw[i][1], bw[j][1], s);
                        s = dp4a_s32(aw[i][2], bw[j][2], s);
                        s = dp4a_s32(aw[i][3], bw[j][3], s);
                        accd[ih * 4 + i][j] = s;
                    }
            }
        }

        #pragma unroll
        for (int i = 0; i < 8; i++) {
            const int lr = r0 + i;
            const float tau = stau[lr];
            #pragma unroll
            for (int j = 0; j < 6; j++) {
                const int lc = c0 + j;
                emit_cand(fmaf(-INV_S2, (float)accd[i][j], sy2[lc]),
                          bm + lr, bn + lc, tau);
            }
        }
    }
}

// ---------------- select: candidate list -> approx top-15 -> exact -----------
__global__ void __launch_bounds__(256) select_kernel(const float* __restrict__ data,
                                                     const float* __restrict__ queue,
                                                     const int* __restrict__ jdx,
                                                     float* __restrict__ out) {
    __shared__ unsigned long long skeys[256 * PERP];
    __shared__ unsigned long long swarp[8];
    __shared__ unsigned long long s_bcast;
    __shared__ unsigned long long sx[PERP];
    __shared__ __align__(16) float sdata[DIM];
    __shared__ int   cand[CANDMAX];
    __shared__ unsigned long long ckeys[CANDMAX];
    __shared__ int   s_cnt, s_nbr;

    const int row = blockIdx.x;
    const int t   = threadIdx.x;
    const int cnt0 = min(g_cnt[row], CAP);
    const unsigned long long* crow = g_cand + (size_t)row * CAP;

    if (t == 0) s_cnt = PERP;
    sdata[t] = data[(size_t)row * DIM + t];

    unsigned long long keys[PERP];
    #pragma unroll
    for (int i = 0; i < PERP; i++) keys[i] = ~0ULL;
    for (int j = t; j < cnt0; j += 256) {
        unsigned long long key = crow[j];
        if (key < keys[PERP - 1]) {
            #pragma unroll
            for (int i = PERP - 1; i >= 1; i--) {
                unsigned long long up = keys[i - 1];
                keys[i] = (key < up) ? up : ((key < keys[i]) ? key : keys[i]);
            }
            keys[0] = (key < keys[0]) ? key : keys[0];
        }
    }
    #pragma unroll
    for (int i = 0; i < PERP; i++) skeys[t * PERP + i] = keys[i];
    __syncthreads();

    for (int it = 0; it < PERP; it++) {
        unsigned long long m = ~0ULL;
        #pragma unroll
        for (int i = 0; i < PERP; i++) {
            unsigned long long v = skeys[t + i * 256];
            m = (v < m) ? v : m;
        }
        #pragma unroll
        for (int o = 16; o; o >>= 1) {
            unsigned long long other = __shfl_xor_sync(0xffffffffu, m, o);
            m = (other < m) ? other : m;
        }
        if ((t & 31) == 0) swarp[t >> 5] = m;
        __syncthreads();
        if (t == 0) {
            unsigned long long mm = swarp[0];
            #pragma unroll
            for (int i = 1; i < 8; i++) mm = (swarp[i] < mm) ? swarp[i] : mm;
            s_bcast = mm;
            sx[it]  = mm;
        }
        __syncthreads();
        unsigned long long cur = s_bcast;
        #pragma unroll
        for (int i = 0; i < PERP; i++) {
            int idx = t + i * 256;
            if (skeys[idx] == cur) skeys[idx] = ~0ULL;
        }
        __syncthreads();
    }

    const unsigned long long tkey = make_key(key_val(sx[PERP - 1]) + DELTA, 0);
    if (t < PERP) cand[t] = (int)(sx[t] & 0xffffffffu);
    #pragma unroll
    for (int i = 0; i < PERP; i++) {
        unsigned long long v = skeys[t + i * 256];
        if (v < tkey) {
            int p = atomicAdd(&s_cnt, 1);
            if (p < CANDMAX) cand[p] = (int)(v & 0xffffffffu);
        }
    }
    __syncthreads();
    const int cnt = (s_cnt < CANDMAX) ? s_cnt : CANDMAX;

    {
        const int lane = t & 31, wid = t >> 5;
        for (int c = wid; c < cnt; c += 8) {
            const int j = cand[c];
            const float* qj = (j < BQ) ? (data + (size_t)j * DIM)
                                       : (queue + (size_t)(j - BQ) * DIM);
            float4 x0 = *(const float4*)&sdata[lane * 8];
            float4 x1 = *(const float4*)&sdata[lane * 8 + 4];
            float4 y0 = *(const float4*)&qj[lane * 8];
            float4 y1 = *(const float4*)&qj[lane * 8 + 4];
            float d = x0.x*y0.x + x0.y*y0.y + x0.z*y0.z + x0.w*y0.w
                    + x1.x*y1.x + x1.y*y1.y + x1.z*y1.z + x1.w*y1.w;
            #pragma unroll
            for (int o = 16; o; o >>= 1) d += __shfl_xor_sync(0xffffffffu, d, o);
            if (lane == 0) ckeys[c] = make_key(fmaf(-2.0f, d, g_y2[j]), j);
        }
    }
    __syncthreads();

    const int r = jdx[row];
    if (t < cnt) {
        unsigned long long mykey = ckeys[t];
        int rank = 0;
        for (int d = 0; d < cnt; d++) rank += (ckeys[d] < mykey);
        if (rank == r) s_nbr = cand[t];
    }
    __syncthreads();
    const int nbr = s_nbr;
    const float* srow = (nbr < BQ) ? (data + (size_t)nbr * DIM)
                                   : (queue + (size_t)(nbr - BQ) * DIM);
    out[(size_t)row * DIM + t] = srow[t];
}

// ---------------- launch -----------------------------------------------------
extern "C" void kernel_launch(void* const* d_in, const int* in_sizes, int n_in,
                              void* d_out, int out_size) {
    (void)in_sizes; (void)n_in; (void)out_size;
    const float* data  = (const float*)d_in[0];
    const float* queue = (const float*)d_in[1];
    const int*   jdx   = (const int*)d_in[2];
    float*       out   = (float*)d_out;

    cudaFuncSetAttribute(gemm_kernel, cudaFuncAttributeMaxDynamicSharedMemorySize, GSMEM);

    prep_kernel<<<QMAX / 4, 256>>>(data, queue);
    gemm_kernel<<<dim3(QMAX / 128, BQ / 128), 256, GSMEM>>>();
    select_kernel<<<BQ, 256>>>(data, queue, jdx, out);
}

// round 15
// speedup vs baseline: 2.5874x; 1.7888x over previous
#include <cuda_runtime.h>
#include <cuda_bf16.h>
#include <cstdint>

#define BQ    1024
#define QMAX  32768
#define DIM   256
#define PERP  15
#define CANDMAX 256
#define SEL_MAX 768
#define DELTA 8.0f
#define QSCALE 20.0f            // int8 quant scale
#define INV_S2 (1.0f/200.0f)    // 2 / (QSCALE*QSCALE)
#define CAP   2048
#define TAU_Z 2.5f

// ---------------- scratch ----------------------------------------------------
__device__ __align__(16) int8_t g_q8[(size_t)QMAX * DIM];
__device__ float g_y2[QMAX];
__device__ unsigned long long g_cand[(size_t)BQ * CAP];
__device__ int   g_cnt[BQ];

// ---------------- prep -------------------------------------------------------
__global__ void __launch_bounds__(256) prep_kernel(const float* __restrict__ data,
                                                   const float* __restrict__ queue) {
    const int t    = threadIdx.x;
    const int row  = blockIdx.x * 4 + (t >> 6);
    const int l    = t & 63;
    const float* src = (row < BQ) ? (data + (size_t)row * DIM)
                                  : (queue + (size_t)(row - BQ) * DIM);
    float4 v = *(const float4*)(src + l * 4);

    int q0 = __float2int_rn(fminf(fmaxf(v.x * QSCALE, -127.f), 127.f));
    int q1 = __float2int_rn(fminf(fmaxf(v.y * QSCALE, -127.f), 127.f));
    int q2 = __float2int_rn(fminf(fmaxf(v.z * QSCALE, -127.f), 127.f));
    int q3 = __float2int_rn(fminf(fmaxf(v.w * QSCALE, -127.f), 127.f));
    uint32_t packed = (uint32_t)(q0 & 0xff) | ((uint32_t)(q1 & 0xff) << 8) |
                      ((uint32_t)(q2 & 0xff) << 16) | ((uint32_t)(q3 & 0xff) << 24);
    *(uint32_t*)(&g_q8[(size_t)row * DIM + l * 4]) = packed;

    float s = v.x*v.x + v.y*v.y + v.z*v.z + v.w*v.w;
    #pragma unroll
    for (int o = 16; o; o >>= 1) s += __shfl_xor_sync(0xffffffffu, s, o);
    __shared__ float ws[8];
    if ((t & 31) == 0) ws[t >> 5] = s;
    __syncthreads();
    if (l == 0) {
        g_y2[row] = ws[(t >> 6) * 2] + ws[(t >> 6) * 2 + 1];
        if (row < BQ) g_cnt[row] = 0;
    }
}

// ---------------- int8 IMMA GEMM (round-8 config), filtering epilogue --------
// CTA tile 128(M) x 128(N) x 64(K-chunk), 4 chunks, double-buffered cp.async.
// 8 warps as 2(m) x 4(n), warp tile 64x32. 41 KB smem -> 2 CTAs/SM.
#define BK      64
#define ROW_STR 80
#define T_BYTES (128 * ROW_STR)             // 10240 per A or B stage
#define OFF_A0  0
#define OFF_A1  T_BYTES
#define OFF_B0  (2 * T_BYTES)
#define OFF_B1  (3 * T_BYTES)
#define OFF_Y2  (4 * T_BYTES)
#define OFF_TAU (OFF_Y2 + 128 * 4)
#define GSMEM   (OFF_TAU + 128 * 4)

__device__ __forceinline__ uint32_t smem_u32(const void* p) {
    uint32_t a;
    asm("{ .reg .u64 t; cvta.to.shared.u64 t, %1; cvt.u32.u64 %0, t; }" : "=r"(a) : "l"(p));
    return a;
}
#define CP_ASYNC16(dst, src) \
    asm volatile("cp.async.cg.shared.global [%0], [%1], 16;" :: "r"(dst), "l"(src))
#define CP_COMMIT() asm volatile("cp.async.commit_group;" ::: "memory")
#define CP_WAIT(n)  asm volatile("cp.async.wait_group %0;" :: "n"(n) : "memory")

__device__ __forceinline__ void ldsm_x4(uint32_t& r0, uint32_t& r1, uint32_t& r2,
                                        uint32_t& r3, uint32_t addr) {
    asm volatile("ldmatrix.sync.aligned.m8n8.x4.shared.b16 {%0,%1,%2,%3}, [%4];"
                 : "=r"(r0), "=r"(r1), "=r"(r2), "=r"(r3) : "r"(addr));
}
__device__ __forceinline__ void mma_s8(int c[4], uint32_t a0, uint32_t a1,
                                       uint32_t a2, uint32_t a3,
                                       uint32_t b0, uint32_t b1) {
    asm volatile(
        "mma.sync.aligned.m16n8k32.row.col.s32.s8.s8.s32 "
        "{%0,%1,%2,%3}, {%4,%5,%6,%7}, {%8,%9}, {%0,%1,%2,%3};\n"
        : "+r"(c[0]), "+r"(c[1]), "+r"(c[2]), "+r"(c[3])
        : "r"(a0), "r"(a1), "r"(a2), "r"(a3), "r"(b0), "r"(b1));
}
__device__ __forceinline__ unsigned long long make_key(float v, int j) {
    unsigned u = __float_as_uint(v);
    u = (u & 0x80000000u) ? ~u : (u | 0x80000000u);
    return ((unsigned long long)u << 32) | (unsigned)j;
}
__device__ __forceinline__ float key_val(unsigned long long k) {
    unsigned s = (unsigned)(k >> 32);
    unsigned u = (s & 0x80000000u) ? (s ^ 0x80000000u) : ~s;
    return __uint_as_float(u);
}
__device__ __forceinline__ void emit_cand(float v, int ri, int cj, float tau) {
    if (v < tau && cj != ri) {
        int p = atomicAdd(&g_cnt[ri], 1);
        if (p < CAP) g_cand[(size_t)ri * CAP + p] = make_key(v, cj);
    }
}

__global__ void __launch_bounds__(256, 2) gemm_kernel() {
    extern __shared__ __align__(16) char smem[];
    const uint32_t sb = smem_u32(smem);
    float* sy2  = (float*)(smem + OFF_Y2);
    float* stau = (float*)(smem + OFF_TAU);

    const int t    = threadIdx.x;
    const int lane = t & 31, wid = t >> 5;
    const int bm   = blockIdx.y * 128;
    const int bn   = blockIdx.x * 128;
    const int wm   = (wid >> 2) * 64;        // 0,64
    const int wn   = (wid & 3) * 32;         // 0..96
    const int gid  = lane >> 2, tig = lane & 3;

    if (t < 32) *(float4*)&sy2[t * 4] = *(const float4*)&g_y2[bn + t * 4];
    if (t < 128) {
        const float x2 = g_y2[bm + t];
        stau[t] = 256.0f - TAU_Z * sqrtf(fmaf(4.0f, x2, 512.0f));
    }

    int acc[4][4][4];
    #pragma unroll
    for (int mi = 0; mi < 4; mi++)
        #pragma unroll
        for (int ni = 0; ni < 4; ni++)
            #pragma unroll
            for (int e = 0; e < 4; e++) acc[mi][ni][e] = 0;

    auto issue = [&](int k0, int buf) {
        const uint32_t abuf = sb + (buf ? OFF_A1 : OFF_A0);
        const uint32_t bbuf = sb + (buf ? OFF_B1 : OFF_B0);
        #pragma unroll
        for (int i = t; i < 512; i += 256) {
            const int r = i >> 2, c = i & 3;
            CP_ASYNC16(abuf + (uint32_t)(r * ROW_STR + c * 16),
                       (const char*)&g_q8[(size_t)(bm + r) * DIM + k0 + c * 16]);
        }
        #pragma unroll
        for (int i = t; i < 512; i += 256) {
            const int r = i >> 2, c = i & 3;
            CP_ASYNC16(bbuf + (uint32_t)(r * ROW_STR + c * 16),
                       (const char*)&g_q8[(size_t)(bn + r) * DIM + k0 + c * 16]);
        }
    };

    issue(0, 0);
    CP_COMMIT();

    for (int kt = 0; kt < 4; kt++) {
        const int buf = kt & 1;
        if (kt + 1 < 4) { issue((kt + 1) * BK, buf ^ 1); CP_COMMIT(); CP_WAIT(1); }
        else           { CP_WAIT(0); }
        __syncthreads();

        const uint32_t abuf = sb + (buf ? OFF_A1 : OFF_A0);
        const uint32_t bbuf = sb + (buf ? OFF_B1 : OFF_B0);
        #pragma unroll
        for (int kk = 0; kk < BK; kk += 32) {
            uint32_t a[4][4], b[4][2];
            const int acol = kk + ((lane >> 4) << 4);
            #pragma unroll
            for (int mi = 0; mi < 4; mi++) {
                const int ar = wm + mi * 16 + (lane & 15);
                ldsm_x4(a[mi][0], a[mi][1], a[mi][2], a[mi][3],
                        abuf + (uint32_t)(ar * ROW_STR + acol));
            }
            const int bcol = kk + (((lane >> 3) & 1) << 4);
            #pragma unroll
            for (int nj = 0; nj < 4; nj += 2) {
                const int br = wn + nj * 8 + (lane & 7) + ((lane >> 4) << 3);
                ldsm_x4(b[nj][0], b[nj][1], b[nj + 1][0], b[nj + 1][1],
                        bbuf + (uint32_t)(br * ROW_STR + bcol));
            }
            #pragma unroll
            for (int mi = 0; mi < 4; mi++)
                #pragma unroll
                for (int ni = 0; ni < 4; ni++)
                    mma_s8(acc[mi][ni], a[mi][0], a[mi][1], a[mi][2], a[mi][3],
                           b[ni][0], b[ni][1]);
        }
        __syncthreads();
    }

    // filtering epilogue: emit v = y2 - 2*dot only when below per-row tau
    #pragma unroll
    for (int mi = 0; mi < 4; mi++) {
        const int lr = wm + mi * 16 + gid;
        const float tau0 = stau[lr], tau1 = stau[lr + 8];
        #pragma unroll
        for (int ni = 0; ni < 4; ni++) {
            const int lc = wn + ni * 8 + tig * 2;
            const float y0 = sy2[lc], y1 = sy2[lc + 1];
            emit_cand(fmaf(-INV_S2, (float)acc[mi][ni][0], y0), bm + lr,     bn + lc,     tau0);
            emit_cand(fmaf(-INV_S2, (float)acc[mi][ni][1], y1), bm + lr,     bn + lc + 1, tau0);
            emit_cand(fmaf(-INV_S2, (float)acc[mi][ni][2], y0), bm + lr + 8, bn + lc,     tau1);
            emit_cand(fmaf(-INV_S2, (float)acc[mi][ni][3], y1), bm + lr + 8, bn + lc + 1, tau1);
        }
    }
}

// ---------------- select v2: n^2 rank on candidate list -> exact -------------
// The per-row candidate list is ~200 entries; find the approx 15th-smallest by
// broadcast rank-count, compact everything under (15th + DELTA), exact-fp32
// rescore those, exact rank-select, gather. Same output as the old machinery.
__global__ void __launch_bounds__(256) select_kernel(const float* __restrict__ data,
                                                     const float* __restrict__ queue,
                                                     const int* __restrict__ jdx,
                                                     float* __restrict__ out) {
    __shared__ unsigned long long skv[SEL_MAX];          // 6 KB
    __shared__ unsigned long long s_thresh;
    __shared__ __align__(16) float sdata[DIM];
    __shared__ int   cand[CANDMAX];
    __shared__ unsigned long long ckeys[CANDMAX];
    __shared__ int   s_cnt, s_nbr;

    const int row = blockIdx.x;
    const int t   = threadIdx.x;
    const int cnt0 = min(g_cnt[row], SEL_MAX);
    const unsigned long long* crow = g_cand + (size_t)row * CAP;

    if (t == 0) { s_cnt = 0; s_thresh = ~0ULL; }
    sdata[t] = data[(size_t)row * DIM + t];
    for (int j = t; j < cnt0; j += 256) skv[j] = crow[j];
    __syncthreads();

    // approx rank via broadcast scan; the (PERP-1)-ranked key sets the threshold
    for (int i = t; i < cnt0; i += 256) {
        const unsigned long long key = skv[i];
        int rank = 0;
        for (int d = 0; d < cnt0; d++) rank += (skv[d] < key);
        if (rank == PERP - 1) s_thresh = key;            // keys unique -> 1 writer
    }
    __syncthreads();

    const unsigned long long tkey = make_key(key_val(s_thresh) + DELTA, 0);
    for (int i = t; i < cnt0; i += 256) {
        const unsigned long long v = skv[i];
        if (v < tkey) {
            int p = atomicAdd(&s_cnt, 1);
            if (p < CANDMAX) cand[p] = (int)(v & 0xffffffffu);
        }
    }
    __syncthreads();
    const int cnt = (s_cnt < CANDMAX) ? s_cnt : CANDMAX;

    // exact fp32 rescore (warp per candidate)
    {
        const int lane = t & 31, wid = t >> 5;
        for (int c = wid; c < cnt; c += 8) {
            const int j = cand[c];
            const float* qj = (j < BQ) ? (data + (size_t)j * DIM)
                                       : (queue + (size_t)(j - BQ) * DIM);
            float4 x0 = *(const float4*)&sdata[lane * 8];
            float4 x1 = *(const float4*)&sdata[lane * 8 + 4];
            float4 y0 = *(const float4*)&qj[lane * 8];
            float4 y1 = *(const float4*)&qj[lane * 8 + 4];
            float d = x0.x*y0.x + x0.y*y0.y + x0.z*y0.z + x0.w*y0.w
                    + x1.x*y1.x + x1.y*y1.y + x1.z*y1.z + x1.w*y1.w;
            #pragma unroll
            for (int o = 16; o; o >>= 1) d += __shfl_xor_sync(0xffffffffu, d, o);
            if (lane == 0) ckeys[c] = make_key(fmaf(-2.0f, d, g_y2[j]), j);
        }
    }
    __syncthreads();

    // exact rank select + gather
    const int r = jdx[row];
    if (t < cnt) {
        unsigned long long mykey = ckeys[t];
        int rank = 0;
        for (int d = 0; d < cnt; d++) rank += (ckeys[d] < mykey);
        if (rank == r) s_nbr = cand[t];
    }
    __syncthreads();
    const int nbr = s_nbr;
    const float* srow = (nbr < BQ) ? (data + (size_t)nbr * DIM)
                                   : (queue + (size_t)(nbr - BQ) * DIM);
    out[(size_t)row * DIM + t] = srow[t];
}

// ---------------- launch -----------------------------------------------------
extern "C" void kernel_launch(void* const* d_in, const int* in_sizes, int n_in,
                              void* d_out, int out_size) {
    (void)in_sizes; (void)n_in; (void)out_size;
    const float* data  = (const float*)d_in[0];
    const float* queue = (const float*)d_in[1];
    const int*   jdx   = (const int*)d_in[2];
    float*       out   = (float*)d_out;

    cudaFuncSetAttribute(gemm_kernel, cudaFuncAttributeMaxDynamicSharedMemorySize, GSMEM);

    prep_kernel<<<QMAX / 4, 256>>>(data, queue);
    gemm_kernel<<<dim3(QMAX / 128, BQ / 128), 256, GSMEM>>>();
    select_kernel<<<BQ, 256>>>(data, queue, jdx, out);
}

// round 16
// speedup vs baseline: 2.6921x; 1.0405x over previous
#include <cuda_runtime.h>
#include <cuda_bf16.h>
#include <cstdint>

#define BQ    1024
#define QMAX  32768
#define DIM   256
#define PERP  15
#define CANDMAX 256
#define SEL_MAX 768
#define DELTA 8.0f
#define QSCALE 20.0f            // int8 quant scale
#define INV_S2 (1.0f/200.0f)    // 2 / (QSCALE*QSCALE)
#define CAP   2048
#define TAU_Z 2.5f

// ---------------- scratch ----------------------------------------------------
__device__ __align__(16) int8_t g_q8[(size_t)QMAX * DIM];
__device__ float g_y2[QMAX];
__device__ unsigned long long g_cand[(size_t)BQ * CAP];
__device__ int   g_cnt[BQ];

// ---------------- prep: one warp per row, MLP=2, no smem/barriers ------------
__device__ __forceinline__ uint32_t quant4(float4 v) {
    int q0 = __float2int_rn(fminf(fmaxf(v.x * QSCALE, -127.f), 127.f));
    int q1 = __float2int_rn(fminf(fmaxf(v.y * QSCALE, -127.f), 127.f));
    int q2 = __float2int_rn(fminf(fmaxf(v.z * QSCALE, -127.f), 127.f));
    int q3 = __float2int_rn(fminf(fmaxf(v.w * QSCALE, -127.f), 127.f));
    return (uint32_t)(q0 & 0xff) | ((uint32_t)(q1 & 0xff) << 8) |
           ((uint32_t)(q2 & 0xff) << 16) | ((uint32_t)(q3 & 0xff) << 24);
}

__global__ void __launch_bounds__(256) prep_kernel(const float* __restrict__ data,
                                                   const float* __restrict__ queue) {
    const int lane = threadIdx.x & 31;
    const int row  = blockIdx.x * 8 + (threadIdx.x >> 5);
    const float* src = (row < BQ) ? (data + (size_t)row * DIM)
                                  : (queue + (size_t)(row - BQ) * DIM);
    // two independent float4 loads per lane (MLP=2)
    float4 v0 = *(const float4*)(src + lane * 4);
    float4 v1 = *(const float4*)(src + 128 + lane * 4);

    uint2 p = make_uint2(quant4(v0), quant4(v1));
    *(uint32_t*)(&g_q8[(size_t)row * DIM + lane * 4])       = p.x;
    *(uint32_t*)(&g_q8[(size_t)row * DIM + 128 + lane * 4]) = p.y;

    float s = v0.x*v0.x + v0.y*v0.y + v0.z*v0.z + v0.w*v0.w
            + v1.x*v1.x + v1.y*v1.y + v1.z*v1.z + v1.w*v1.w;
    #pragma unroll
    for (int o = 16; o; o >>= 1) s += __shfl_xor_sync(0xffffffffu, s, o);
    if (lane == 0) {
        g_y2[row] = s;
        if (row < BQ) g_cnt[row] = 0;
    }
}

// ---------------- int8 IMMA GEMM (round-8 config), filtering epilogue --------
// CTA tile 128(M) x 128(N) x 64(K-chunk), 4 chunks, double-buffered cp.async.
// 8 warps as 2(m) x 4(n), warp tile 64x32. 41 KB smem -> 2 CTAs/SM.
#define BK      64
#define ROW_STR 80
#define T_BYTES (128 * ROW_STR)             // 10240 per A or B stage
#define OFF_A0  0
#define OFF_A1  T_BYTES
#define OFF_B0  (2 * T_BYTES)
#define OFF_B1  (3 * T_BYTES)
#define OFF_Y2  (4 * T_BYTES)
#define OFF_TAU (OFF_Y2 + 128 * 4)
#define GSMEM   (OFF_TAU + 128 * 4)

__device__ __forceinline__ uint32_t smem_u32(const void* p) {
    uint32_t a;
    asm("{ .reg .u64 t; cvta.to.shared.u64 t, %1; cvt.u32.u64 %0, t; }" : "=r"(a) : "l"(p));
    return a;
}
#define CP_ASYNC16(dst, src) \
    asm volatile("cp.async.cg.shared.global [%0], [%1], 16;" :: "r"(dst), "l"(src))
#define CP_COMMIT() asm volatile("cp.async.commit_group;" ::: "memory")
#define CP_WAIT(n)  asm volatile("cp.async.wait_group %0;" :: "n"(n) : "memory")

__device__ __forceinline__ void ldsm_x4(uint32_t& r0, uint32_t& r1, uint32_t& r2,
                                        uint32_t& r3, uint32_t addr) {
    asm volatile("ldmatrix.sync.aligned.m8n8.x4.shared.b16 {%0,%1,%2,%3}, [%4];"
                 : "=r"(r0), "=r"(r1), "=r"(r2), "=r"(r3) : "r"(addr));
}
__device__ __forceinline__ void mma_s8(int c[4], uint32_t a0, uint32_t a1,
                                       uint32_t a2, uint32_t a3,
                                       uint32_t b0, uint32_t b1) {
    asm volatile(
        "mma.sync.aligned.m16n8k32.row.col.s32.s8.s8.s32 "
        "{%0,%1,%2,%3}, {%4,%5,%6,%7}, {%8,%9}, {%0,%1,%2,%3};\n"
        : "+r"(c[0]), "+r"(c[1]), "+r"(c[2]), "+r"(c[3])
        : "r"(a0), "r"(a1), "r"(a2), "r"(a3), "r"(b0), "r"(b1));
}
__device__ __forceinline__ unsigned long long make_key(float v, int j) {
    unsigned u = __float_as_uint(v);
    u = (u & 0x80000000u) ? ~u : (u | 0x80000000u);
    return ((unsigned long long)u << 32) | (unsigned)j;
}
__device__ __forceinline__ float key_val(unsigned long long k) {
    unsigned s = (unsigned)(k >> 32);
    unsigned u = (s & 0x80000000u) ? (s ^ 0x80000000u) : ~s;
    return __uint_as_float(u);
}
__device__ __forceinline__ void emit_cand(float v, int ri, int cj, float tau) {
    if (v < tau && cj != ri) {
        int p = atomicAdd(&g_cnt[ri], 1);
        if (p < CAP) g_cand[(size_t)ri * CAP + p] = make_key(v, cj);
    }
}

__global__ void __launch_bounds__(256, 2) gemm_kernel() {
    extern __shared__ __align__(16) char smem[];
    const uint32_t sb = smem_u32(smem);
    float* sy2  = (float*)(smem + OFF_Y2);
    float* stau = (float*)(smem + OFF_TAU);

    const int t    = threadIdx.x;
    const int lane = t & 31, wid = t >> 5;
    const int bm   = blockIdx.y * 128;
    const int bn   = blockIdx.x * 128;
    const int wm   = (wid >> 2) * 64;        // 0,64
    const int wn   = (wid & 3) * 32;         // 0..96
    const int gid  = lane >> 2, tig = lane & 3;

    if (t < 32) *(float4*)&sy2[t * 4] = *(const float4*)&g_y2[bn + t * 4];
    if (t < 128) {
        const float x2 = g_y2[bm + t];
        stau[t] = 256.0f - TAU_Z * sqrtf(fmaf(4.0f, x2, 512.0f));
    }

    int acc[4][4][4];
    #pragma unroll
    for (int mi = 0; mi < 4; mi++)
        #pragma unroll
        for (int ni = 0; ni < 4; ni++)
            #pragma unroll
            for (int e = 0; e < 4; e++) acc[mi][ni][e] = 0;

    auto issue = [&](int k0, int buf) {
        const uint32_t abuf = sb + (buf ? OFF_A1 : OFF_A0);
        const uint32_t bbuf = sb + (buf ? OFF_B1 : OFF_B0);
        #pragma unroll
        for (int i = t; i < 512; i += 256) {
            const int r = i >> 2, c = i & 3;
            CP_ASYNC16(abuf + (uint32_t)(r * ROW_STR + c * 16),
                       (const char*)&g_q8[(size_t)(bm + r) * DIM + k0 + c * 16]);
        }
        #pragma unroll
        for (int i = t; i < 512; i += 256) {
            const int r = i >> 2, c = i & 3;
            CP_ASYNC16(bbuf + (uint32_t)(r * ROW_STR + c * 16),
                       (const char*)&g_q8[(size_t)(bn + r) * DIM + k0 + c * 16]);
        }
    };

    issue(0, 0);
    CP_COMMIT();

    for (int kt = 0; kt < 4; kt++) {
        const int buf = kt & 1;
        if (kt + 1 < 4) { issue((kt + 1) * BK, buf ^ 1); CP_COMMIT(); CP_WAIT(1); }
        else           { CP_WAIT(0); }
        __syncthreads();

        const uint32_t abuf = sb + (buf ? OFF_A1 : OFF_A0);
        const uint32_t bbuf = sb + (buf ? OFF_B1 : OFF_B0);
        #pragma unroll
        for (int kk = 0; kk < BK; kk += 32) {
            uint32_t a[4][4], b[4][2];
            const int acol = kk + ((lane >> 4) << 4);
            #pragma unroll
            for (int mi = 0; mi < 4; mi++) {
                const int ar = wm + mi * 16 + (lane & 15);
                ldsm_x4(a[mi][0], a[mi][1], a[mi][2], a[mi][3],
                        abuf + (uint32_t)(ar * ROW_STR + acol));
            }
            const int bcol = kk + (((lane >> 3) & 1) << 4);
            #pragma unroll
            for (int nj = 0; nj < 4; nj += 2) {
                const int br = wn + nj * 8 + (lane & 7) + ((lane >> 4) << 3);
                ldsm_x4(b[nj][0], b[nj][1], b[nj + 1][0], b[nj + 1][1],
                        bbuf + (uint32_t)(br * ROW_STR + bcol));
            }
            #pragma unroll
            for (int mi = 0; mi < 4; mi++)
                #pragma unroll
                for (int ni = 0; ni < 4; ni++)
                    mma_s8(acc[mi][ni], a[mi][0], a[mi][1], a[mi][2], a[mi][3],
                           b[ni][0], b[ni][1]);
        }
        __syncthreads();
    }

    // filtering epilogue: emit v = y2 - 2*dot only when below per-row tau
    #pragma unroll
    for (int mi = 0; mi < 4; mi++) {
        const int lr = wm + mi * 16 + gid;
        const float tau0 = stau[lr], tau1 = stau[lr + 8];
        #pragma unroll
        for (int ni = 0; ni < 4; ni++) {
            const int lc = wn + ni * 8 + tig * 2;
            const float y0 = sy2[lc], y1 = sy2[lc + 1];
            emit_cand(fmaf(-INV_S2, (float)acc[mi][ni][0], y0), bm + lr,     bn + lc,     tau0);
            emit_cand(fmaf(-INV_S2, (float)acc[mi][ni][1], y1), bm + lr,     bn + lc + 1, tau0);
            emit_cand(fmaf(-INV_S2, (float)acc[mi][ni][2], y0), bm + lr + 8, bn + lc,     tau1);
            emit_cand(fmaf(-INV_S2, (float)acc[mi][ni][3], y1), bm + lr + 8, bn + lc + 1, tau1);
        }
    }
}

// ---------------- select v2: n^2 rank on candidate list -> exact -------------
__global__ void __launch_bounds__(256) select_kernel(const float* __restrict__ data,
                                                     const float* __restrict__ queue,
                                                     const int* __restrict__ jdx,
                                                     float* __restrict__ out) {
    __shared__ unsigned long long skv[SEL_MAX];          // 6 KB
    __shared__ unsigned long long s_thresh;
    __shared__ __align__(16) float sdata[DIM];
    __shared__ int   cand[CANDMAX];
    __shared__ unsigned long long ckeys[CANDMAX];
    __shared__ int   s_cnt, s_nbr;

    const int row = blockIdx.x;
    const int t   = threadIdx.x;
    const int cnt0 = min(g_cnt[row], SEL_MAX);
    const unsigned long long* crow = g_cand + (size_t)row * CAP;

    if (t == 0) { s_cnt = 0; s_thresh = ~0ULL; }
    sdata[t] = data[(size_t)row * DIM + t];
    for (int j = t; j < cnt0; j += 256) skv[j] = crow[j];
    __syncthreads();

    // approx rank via broadcast scan; the (PERP-1)-ranked key sets the threshold
    for (int i = t; i < cnt0; i += 256) {
        const unsigned long long key = skv[i];
        int rank = 0;
        for (int d = 0; d < cnt0; d++) rank += (skv[d] < key);
        if (rank == PERP - 1) s_thresh = key;            // keys unique -> 1 writer
    }
    __syncthreads();

    const unsigned long long tkey = make_key(key_val(s_thresh) + DELTA, 0);
    for (int i = t; i < cnt0; i += 256) {
        const unsigned long long v = skv[i];
        if (v < tkey) {
            int p = atomicAdd(&s_cnt, 1);
            if (p < CANDMAX) cand[p] = (int)(v & 0xffffffffu);
        }
    }
    __syncthreads();
    const int cnt = (s_cnt < CANDMAX) ? s_cnt : CANDMAX;

    // exact fp32 rescore (warp per candidate)
    {
        const int lane = t & 31, wid = t >> 5;
        for (int c = wid; c < cnt; c += 8) {
            const int j = cand[c];
            const float* qj = (j < BQ) ? (data + (size_t)j * DIM)
                                       : (queue + (size_t)(j - BQ) * DIM);
            float4 x0 = *(const float4*)&sdata[lane * 8];
            float4 x1 = *(const float4*)&sdata[lane * 8 + 4];
            float4 y0 = *(const float4*)&qj[lane * 8];
            float4 y1 = *(const float4*)&qj[lane * 8 + 4];
            float d = x0.x*y0.x + x0.y*y0.y + x0.z*y0.z + x0.w*y0.w
                    + x1.x*y1.x + x1.y*y1.y + x1.z*y1.z + x1.w*y1.w;
            #pragma unroll
            for (int o = 16; o; o >>= 1) d += __shfl_xor_sync(0xffffffffu, d, o);
            if (lane == 0) ckeys[c] = make_key(fmaf(-2.0f, d, g_y2[j]), j);
        }
    }
    __syncthreads();

    // exact rank select + gather
    const int r = jdx[row];
    if (t < cnt) {
        unsigned long long mykey = ckeys[t];
        int rank = 0;
        for (int d = 0; d < cnt; d++) rank += (ckeys[d] < mykey);
        if (rank == r) s_nbr = cand[t];
    }
    __syncthreads();
    const int nbr = s_nbr;
    const float* srow = (nbr < BQ) ? (data + (size_t)nbr * DIM)
                                   : (queue + (size_t)(nbr - BQ) * DIM);
    out[(size_t)row * DIM + t] = srow[t];
}

// ---------------- launch -----------------------------------------------------
extern "C" void kernel_launch(void* const* d_in, const int* in_sizes, int n_in,
                              void* d_out, int out_size) {
    (void)in_sizes; (void)n_in; (void)out_size;
    const float* data  = (const float*)d_in[0];
    const float* queue = (const float*)d_in[1];
    const int*   jdx   = (const int*)d_in[2];
    float*       out   = (float*)d_out;

    cudaFuncSetAttribute(gemm_kernel, cudaFuncAttributeMaxDynamicSharedMemorySize, GSMEM);

    prep_kernel<<<QMAX / 8, 256>>>(data, queue);
    gemm_kernel<<<dim3(QMAX / 128, BQ / 128), 256, GSMEM>>>();
    select_kernel<<<BQ, 256>>>(data, queue, jdx, out);
}